// round 3
// baseline (speedup 1.0000x reference)
#include <cuda_runtime.h>

// ---------------- problem constants ----------------
constexpr int Bz = 4, Cn = 128, Hh = 128, Wd = 128;
constexpr int HW = Hh * Wd;       // 16384
constexpr int P  = Bz * HW;       // 65536 pixels
constexpr int NCH = 256, CL = 64; // scan: 256 chunks of 64 steps (L = 16384)

// ---------------- scratch (device globals; no allocation allowed) ----------------
__device__ float g_xin [P * Cn];
__device__ float g_xc  [P * Cn];
__device__ float g_xd  [P * Cn];
__device__ float g_a   [P * Cn];
__device__ float g_bx  [P * Cn];
__device__ float g_C   [P];
__device__ float g_y   [P * Cn];
__device__ float g_As  [Bz * NCH * Cn];
__device__ float g_Bs  [Bz * NCH * Cn];
__device__ float g_hin [Bz * NCH * Cn];

// =====================================================================
// K1: in_proj 1x1 GEMM.  x (B,C,HW) channel-major -> xin channels-last (p,c)
// tile: 128 pixels x 128 outputs, 256 threads, 8x8 microtile
// =====================================================================
__global__ void k_in_proj(const float* __restrict__ x, const float* __restrict__ w) {
    extern __shared__ float sm[];
    float* Ws = sm;               // [128][132]  Ws[c*132+o] = w[o][c]
    float* Xs = sm + 128 * 132;   // [128][132]  Xs[c*132+j] = x[c][pix j]
    const int t  = threadIdx.x;
    const int p0 = blockIdx.x * 128;
    const int b  = p0 / HW, hw0 = p0 % HW;

    for (int i = t; i < 128 * 128; i += 256) {
        int o = i >> 7, c = i & 127;
        Ws[c * 132 + o] = w[i];
    }
    for (int i = t; i < 128 * 128; i += 256) {
        int c = i >> 7, j = i & 127;
        Xs[c * 132 + j] = x[(b * Cn + c) * HW + hw0 + j];
    }
    __syncthreads();

    const int tx = t & 15, ty = t >> 4;   // tx: pixel group (8), ty: output group (8)
    float acc[8][8];
#pragma unroll
    for (int i = 0; i < 8; i++)
#pragma unroll
        for (int j = 0; j < 8; j++) acc[i][j] = 0.f;

#pragma unroll 2
    for (int c = 0; c < 128; ++c) {
        float4 x0 = *(const float4*)&Xs[c * 132 + tx * 8];
        float4 x1 = *(const float4*)&Xs[c * 132 + tx * 8 + 4];
        float4 w0 = *(const float4*)&Ws[c * 132 + ty * 8];
        float4 w1 = *(const float4*)&Ws[c * 132 + ty * 8 + 4];
        float xv[8] = {x0.x, x0.y, x0.z, x0.w, x1.x, x1.y, x1.z, x1.w};
        float wv[8] = {w0.x, w0.y, w0.z, w0.w, w1.x, w1.y, w1.z, w1.w};
#pragma unroll
        for (int i = 0; i < 8; i++)
#pragma unroll
            for (int j = 0; j < 8; j++) acc[i][j] += xv[i] * wv[j];
    }
#pragma unroll
    for (int i = 0; i < 8; i++) {
        float* dst = &g_xin[(size_t)(p0 + tx * 8 + i) * Cn + ty * 8];
        *(float4*)(dst)     = make_float4(acc[i][0], acc[i][1], acc[i][2], acc[i][3]);
        *(float4*)(dst + 4) = make_float4(acc[i][4], acc[i][5], acc[i][6], acc[i][7]);
    }
}

// =====================================================================
// K2: depthwise 3x3 conv + bias + SiLU  (channels-last, zero-pad SAME)
// 256 threads = 8 pixels x 32 channel-groups (float4)
// =====================================================================
__global__ void k_dwsilu(const float* __restrict__ w, const float* __restrict__ bias) {
    __shared__ float sw[9 * 128];
    __shared__ float sb[128];
    const int t = threadIdx.x;
    for (int i = t; i < 1152; i += 256) {
        int c = i / 9, k = i - c * 9;
        sw[k * 128 + c] = w[i];
    }
    if (t < 128) sb[t] = bias[t];
    __syncthreads();

    const int p  = blockIdx.x * 8 + (t >> 5);
    const int cg = t & 31;
    const int b = p / HW, hw = p % HW, yy = hw / Wd, xx = hw % Wd;
    float4 acc = *(const float4*)&sb[cg * 4];
#pragma unroll
    for (int ky = 0; ky < 3; ky++) {
        int yv = yy + ky - 1;
        if ((unsigned)yv >= (unsigned)Hh) continue;
#pragma unroll
        for (int kx = 0; kx < 3; kx++) {
            int xv = xx + kx - 1;
            if ((unsigned)xv >= (unsigned)Wd) continue;
            float4 v  = *(const float4*)&g_xin[(size_t)(b * HW + yv * Wd + xv) * Cn + cg * 4];
            float4 wv = *(const float4*)&sw[(ky * 3 + kx) * 128 + cg * 4];
            acc.x += wv.x * v.x; acc.y += wv.y * v.y;
            acc.z += wv.z * v.z; acc.w += wv.w * v.w;
        }
    }
    float4 r;
    r.x = acc.x / (1.f + __expf(-acc.x));
    r.y = acc.y / (1.f + __expf(-acc.y));
    r.z = acc.z / (1.f + __expf(-acc.z));
    r.w = acc.w / (1.f + __expf(-acc.w));
    *(float4*)&g_xc[(size_t)p * Cn + cg * 4] = r;
}

__device__ __forceinline__ float softplusf(float x) {
    return fmaxf(x, 0.f) + log1pf(__expf(-fabsf(x)));
}

// =====================================================================
// K3 fused: dwconv -> LN -> GELU -> offsets -> DCNv3 -> x_dbl -> a/bx/C
// one block per pixel, 128 threads (= channels)
// =====================================================================
__global__ void k_fused(const float* __restrict__ w, const float* __restrict__ bias,
                        const float* __restrict__ lng, const float* __restrict__ lnb,
                        const float* __restrict__ offw, const float* __restrict__ offb,
                        const float* __restrict__ xpw,
                        const float* __restrict__ dtw, const float* __restrict__ dtb,
                        const float* __restrict__ alog) {
    __shared__ float s[128];
    __shared__ float sxd[128];
    __shared__ float sxb[10];
    __shared__ float soff[16];
    __shared__ float red[8];
    __shared__ float smr[2];
    const int c = threadIdx.x;
    const int p = blockIdx.x;
    const int b = p >> 14, hw = p & 16383, yy = hw >> 7, xx = hw & 127;

    // -------- dwconv (dw_w) + bias --------
    float acc = bias[c];
#pragma unroll
    for (int ky = 0; ky < 3; ky++) {
        int yv = yy + ky - 1;
        if ((unsigned)yv >= (unsigned)Hh) continue;
#pragma unroll
        for (int kx = 0; kx < 3; kx++) {
            int xv = xx + kx - 1;
            if ((unsigned)xv >= (unsigned)Wd) continue;
            acc += w[c * 9 + ky * 3 + kx] * g_xc[(size_t)(b * HW + yv * Wd + xv) * Cn + c];
        }
    }
    // -------- LN over channels --------
    const float v = acc;
    float s1 = v, s2 = v * v;
#pragma unroll
    for (int o = 16; o; o >>= 1) {
        s1 += __shfl_down_sync(0xffffffffu, s1, o);
        s2 += __shfl_down_sync(0xffffffffu, s2, o);
    }
    const int wid = c >> 5;
    if ((c & 31) == 0) { red[wid] = s1; red[4 + wid] = s2; }
    __syncthreads();
    if (c == 0) {
        float a  = red[0] + red[1] + red[2] + red[3];
        float bq = red[4] + red[5] + red[6] + red[7];
        float m  = a * (1.f / 128.f);
        float var = bq * (1.f / 128.f) - m * m;
        smr[0] = m; smr[1] = rsqrtf(var + 1e-6f);
    }
    __syncthreads();
    float xn = (v - smr[0]) * smr[1] * lng[c] + lnb[c];
    s[c] = 0.5f * xn * (1.f + erff(xn * 0.70710678118654752f));
    __syncthreads();

    // -------- offsets: 16 outputs, 8 lanes each --------
    {
        const int o = c >> 3, seg = c & 7;
        float a2 = 0.f;
#pragma unroll
        for (int k = 0; k < 16; k++) a2 += s[seg * 16 + k] * offw[o * 128 + seg * 16 + k];
#pragma unroll
        for (int d = 4; d; d >>= 1) a2 += __shfl_down_sync(0xffffffffu, a2, d, 8);
        if (seg == 0) soff[o] = a2 + offb[o];
    }
    __syncthreads();

    // -------- DCNv3 bilinear sample (zero-padding) --------
    {
        const int g = c >> 4;
        const float px = (float)xx + soff[g * 2];
        const float py = (float)yy + soff[g * 2 + 1];
        const float x0 = floorf(px), y0 = floorf(py);
        const float wx = px - x0, wy = py - y0;
        float ad = 0.f;
#pragma unroll
        for (int dy = 0; dy < 2; dy++) {
#pragma unroll
            for (int dx = 0; dx < 2; dx++) {
                float yif = y0 + (float)dy, xif = x0 + (float)dx;
                float wgt = (dy ? wy : 1.f - wy) * (dx ? wx : 1.f - wx);
                bool valid = (yif >= 0.f) && (yif < (float)Hh) && (xif >= 0.f) && (xif < (float)Wd);
                int yi = (int)fminf(fmaxf(yif, 0.f), (float)(Hh - 1));
                int xi = (int)fminf(fmaxf(xif, 0.f), (float)(Wd - 1));
                float vv = g_xc[(size_t)(b * HW + yi * Wd + xi) * Cn + c];
                ad += vv * (valid ? wgt : 0.f);
            }
        }
        sxd[c] = ad;
        g_xd[(size_t)p * Cn + c] = ad;
    }
    __syncthreads();

    // -------- x_dbl = x_proj_w (10x128) @ xd --------
    {
        const int oo = c >> 3, sg = c & 7;
        float a3 = 0.f;
        if (oo < 10) {
#pragma unroll
            for (int k = 0; k < 16; k++)
                a3 += sxd[sg * 16 + k] * xpw[oo * 128 + sg * 16 + k];
        }
#pragma unroll
        for (int d = 4; d; d >>= 1) a3 += __shfl_down_sync(0xffffffffu, a3, d, 8);
        if (sg == 0 && oo < 10) sxb[oo] = a3;
    }
    __syncthreads();

    // -------- delta -> a, bx, C --------
    {
        float4 w0 = *(const float4*)&dtw[c * 8];
        float4 w1 = *(const float4*)&dtw[c * 8 + 4];
        float dtr = dtb[c]
            + w0.x * sxb[0] + w0.y * sxb[1] + w0.z * sxb[2] + w0.w * sxb[3]
            + w1.x * sxb[4] + w1.y * sxb[5] + w1.z * sxb[6] + w1.w * sxb[7];
        float delta = softplusf(dtr);
        float a = __expf(-__expf(alog[c]) * delta);
        float bxv = delta * sxb[8] * sxd[c];
        g_a [(size_t)p * Cn + c] = a;
        g_bx[(size_t)p * Cn + c] = bxv;
        if (c == 0) g_C[p] = sxb[9];
    }
}

// =====================================================================
// K4: scan pass 1 — per-chunk summaries (A = prod a, B = local h)
// =====================================================================
__global__ void k_scan1() {
    const int d = threadIdx.x;
    const int chunk = blockIdx.x, b = blockIdx.y;
    float Ar = 1.f, h = 0.f;
    size_t base = ((size_t)(b * HW + chunk * CL)) * Cn + d;
#pragma unroll 4
    for (int i = 0; i < CL; i++) {
        float a  = g_a [base + (size_t)i * Cn];
        float bx = g_bx[base + (size_t)i * Cn];
        Ar *= a;
        h = a * h + bx;
    }
    const int idx = (b * NCH + chunk) * Cn + d;
    g_As[idx] = Ar;
    g_Bs[idx] = h;
}

// K5: scan pass 2 — sequential combine of chunk summaries per (b,d)
__global__ void k_scan2() {
    const int b = blockIdx.x, d = threadIdx.x;
    float h = 0.f;
    for (int ch = 0; ch < NCH; ch++) {
        const int idx = (b * NCH + ch) * Cn + d;
        g_hin[idx] = h;
        h = g_As[idx] * h + g_Bs[idx];
    }
}

// K6: scan pass 3 — stream with known h_in, y = h*C + Ds*x
__global__ void k_scan3(const float* __restrict__ Ds) {
    const int d = threadIdx.x;
    const int chunk = blockIdx.x, b = blockIdx.y;
    const float Dd = Ds[d];
    float h = g_hin[(b * NCH + chunk) * Cn + d];
    const int pbase = b * HW + chunk * CL;
    size_t base = (size_t)pbase * Cn + d;
#pragma unroll 4
    for (int i = 0; i < CL; i++) {
        float a  = g_a [base + (size_t)i * Cn];
        float bx = g_bx[base + (size_t)i * Cn];
        float xv = g_xd[base + (size_t)i * Cn];
        h = a * h + bx;
        g_y[base + (size_t)i * Cn] = h * g_C[pbase + i] + Dd * xv;
    }
}

// =====================================================================
// K7: out LayerNorm (fused) + out_proj GEMM. 128 pixels x 128 outputs/block
// =====================================================================
__global__ void k_out_proj(const float* __restrict__ w, const float* __restrict__ lng,
                           const float* __restrict__ lnb, float* __restrict__ out) {
    extern __shared__ float sm[];
    float* Ws    = sm;                 // 128*132
    float* Ys    = sm + 128 * 132;     // 128*132
    float* sred  = Ys + 128 * 132;     // 256
    float* s2red = sred + 256;         // 256
    float* smean = s2red + 256;        // 128
    float* srstd = smean + 128;        // 128
    const int t  = threadIdx.x;
    const int p0 = blockIdx.x * 128;
    const int b  = p0 / HW, hw0 = p0 % HW;

    for (int i = t; i < 128 * 128; i += 256) {
        int o = i >> 7, c = i & 127;
        Ws[c * 132 + o] = w[i];
    }
    for (int i = t; i < 128 * 128; i += 256) {
        int c = i & 127, j = i >> 7;
        Ys[c * 132 + j] = g_y[(size_t)(p0 + j) * Cn + c];
    }
    __syncthreads();

    // fused LN over channels, per pixel j
    const int j = t & 127, part = t >> 7;   // part in {0,1}, 64 channels each
    {
        float s = 0.f, s2 = 0.f;
        for (int c = part * 64; c < part * 64 + 64; c++) {
            float v = Ys[c * 132 + j];
            s += v; s2 += v * v;
        }
        sred [part * 128 + j] = s;
        s2red[part * 128 + j] = s2;
    }
    __syncthreads();
    if (t < 128) {
        float a  = sred [t] + sred [128 + t];
        float bq = s2red[t] + s2red[128 + t];
        float m = a * (1.f / 128.f);
        float var = bq * (1.f / 128.f) - m * m;
        smean[t] = m;
        srstd[t] = rsqrtf(var + 1e-6f);
    }
    __syncthreads();
    {
        const float m = smean[j], r = srstd[j];
        for (int c = part * 64; c < part * 64 + 64; c++) {
            float v = Ys[c * 132 + j];
            Ys[c * 132 + j] = (v - m) * r * lng[c] + lnb[c];
        }
    }
    __syncthreads();

    const int tx = t & 15, ty = t >> 4;
    float acc[8][8];
#pragma unroll
    for (int i = 0; i < 8; i++)
#pragma unroll
        for (int jo = 0; jo < 8; jo++) acc[i][jo] = 0.f;

#pragma unroll 2
    for (int c = 0; c < 128; ++c) {
        float4 x0 = *(const float4*)&Ys[c * 132 + tx * 8];
        float4 x1 = *(const float4*)&Ys[c * 132 + tx * 8 + 4];
        float4 w0 = *(const float4*)&Ws[c * 132 + ty * 8];
        float4 w1 = *(const float4*)&Ws[c * 132 + ty * 8 + 4];
        float xv[8] = {x0.x, x0.y, x0.z, x0.w, x1.x, x1.y, x1.z, x1.w};
        float wv[8] = {w0.x, w0.y, w0.z, w0.w, w1.x, w1.y, w1.z, w1.w};
#pragma unroll
        for (int i = 0; i < 8; i++)
#pragma unroll
            for (int jo = 0; jo < 8; jo++) acc[i][jo] += xv[i] * wv[jo];
    }
#pragma unroll
    for (int jo = 0; jo < 8; jo++) {
        int o = ty * 8 + jo;
        *(float4*)&out[(size_t)(b * Cn + o) * HW + hw0 + tx * 8] =
            make_float4(acc[0][jo], acc[1][jo], acc[2][jo], acc[3][jo]);
        *(float4*)&out[(size_t)(b * Cn + o) * HW + hw0 + tx * 8 + 4] =
            make_float4(acc[4][jo], acc[5][jo], acc[6][jo], acc[7][jo]);
    }
}

// =====================================================================
extern "C" void kernel_launch(void* const* d_in, const int* in_sizes, int n_in,
                              void* d_out, int out_size) {
    const float* x      = (const float*)d_in[0];
    const float* inw    = (const float*)d_in[1];
    const float* c2w    = (const float*)d_in[2];
    const float* c2b    = (const float*)d_in[3];
    const float* dww    = (const float*)d_in[4];
    const float* dwb    = (const float*)d_in[5];
    const float* dlng   = (const float*)d_in[6];
    const float* dlnb   = (const float*)d_in[7];
    const float* offw   = (const float*)d_in[8];
    const float* offb   = (const float*)d_in[9];
    const float* xpw    = (const float*)d_in[10];
    const float* dtw    = (const float*)d_in[11];
    const float* dtb    = (const float*)d_in[12];
    const float* alog   = (const float*)d_in[13];
    const float* Ds     = (const float*)d_in[14];
    const float* olng   = (const float*)d_in[15];
    const float* olnb   = (const float*)d_in[16];
    const float* outw   = (const float*)d_in[17];
    float* out = (float*)d_out;

    const int smem_in  = (128 * 132 * 2) * 4;
    const int smem_out = (128 * 132 * 2 + 256 + 256 + 128 + 128) * 4;
    cudaFuncSetAttribute(k_in_proj,  cudaFuncAttributeMaxDynamicSharedMemorySize, smem_in);
    cudaFuncSetAttribute(k_out_proj, cudaFuncAttributeMaxDynamicSharedMemorySize, smem_out);

    k_in_proj<<<P / 128, 256, smem_in>>>(x, inw);
    k_dwsilu<<<P / 8, 256>>>(c2w, c2b);
    k_fused<<<P, 128>>>(dww, dwb, dlng, dlnb, offw, offb, xpw, dtw, dtb, alog);
    k_scan1<<<dim3(NCH, Bz), 128>>>();
    k_scan2<<<Bz, 128>>>();
    k_scan3<<<dim3(NCH, Bz), 128>>>(Ds);
    k_out_proj<<<P / 128, 256, smem_out>>>(outw, olng, olnb, out);
}

// round 6
// speedup vs baseline: 1.1585x; 1.1585x over previous
#include <cuda_runtime.h>
#include <cuda_bf16.h>
#include <cstdint>

// ---------------- problem constants ----------------
constexpr int Bz = 4, Cn = 128, Hh = 128, Wd = 128;
constexpr int HW = Hh * Wd;       // 16384
constexpr int P  = Bz * HW;       // 65536 pixels
constexpr int NCH = 256, CL = 64; // scan: 256 chunks of 64 steps

// ---------------- scratch ----------------
__device__ float g_xin [P * Cn];
__device__ float g_xc  [P * Cn];
__device__ float g_off [P * 16];
__device__ float g_xd  [P * Cn];
__device__ float g_a   [P * Cn];
__device__ float g_bx  [P * Cn];
__device__ float g_C   [P];
__device__ float g_y   [P * Cn];
__device__ float g_As  [Bz * NCH * Cn];
__device__ float g_Bs  [Bz * NCH * Cn];
__device__ float g_hin [Bz * NCH * Cn];
// bf16 hi/lo weight images, row-major [o][c]
__device__ __align__(16) unsigned short g_wbhi_in [16384];
__device__ __align__(16) unsigned short g_wblo_in [16384];
__device__ __align__(16) unsigned short g_wbhi_out[16384];
__device__ __align__(16) unsigned short g_wblo_out[16384];

__device__ __forceinline__ uint32_t smem_to_u32(const void* p) {
    uint32_t a;
    asm("{ .reg .u64 t; cvta.to.shared.u64 t, %1; cvt.u32.u64 %0, t; }" : "=r"(a) : "l"(p));
    return a;
}

// smem tile layout: row stride 256B (128 bf16), 16B chunks XOR-swizzled by row
__device__ __forceinline__ uint32_t sw_off(int row, int k) {
    int chunk = k >> 3;
    int swch = (chunk & 8) | ((chunk ^ row) & 7);
    return (uint32_t)(row * 256 + swch * 16 + (k & 7) * 2);
}

#define LDSM_X4(r0, r1, r2, r3, addr) \
    asm volatile("ldmatrix.sync.aligned.m8n8.x4.shared.b16 {%0,%1,%2,%3}, [%4];" \
                 : "=r"(r0), "=r"(r1), "=r"(r2), "=r"(r3) : "r"(addr))
#define MMA16816(d, a, b0v, b1v) \
    asm volatile("mma.sync.aligned.m16n8k16.row.col.f32.bf16.bf16.f32 " \
                 "{%0,%1,%2,%3}, {%4,%5,%6,%7}, {%8,%9}, {%0,%1,%2,%3};" \
                 : "+f"((d)[0]), "+f"((d)[1]), "+f"((d)[2]), "+f"((d)[3]) \
                 : "r"((a)[0]), "r"((a)[1]), "r"((a)[2]), "r"((a)[3]), "r"(b0v), "r"(b1v))

// dyn smem layout for GEMM kernels (128KB)
constexpr int SM_A_HI = 0, SM_A_LO = 32768, SM_B_HI = 65536, SM_B_LO = 98304;
constexpr int SM_GEMM = 131072;

// =====================================================================
// K0: split weights into bf16 hi/lo (row-major [o][c])
// =====================================================================
__global__ void k_prep_w(const float* __restrict__ inw, const float* __restrict__ outw) {
    int idx = blockIdx.x * 256 + threadIdx.x;   // 32768 total
    int which = idx >> 14, rem = idx & 16383;
    float v = (which ? outw : inw)[rem];
    __nv_bfloat16 h = __float2bfloat16(v);
    __nv_bfloat16 l = __float2bfloat16(v - __bfloat162float(h));
    if (which) { g_wbhi_out[rem] = __bfloat16_as_ushort(h); g_wblo_out[rem] = __bfloat16_as_ushort(l); }
    else       { g_wbhi_in [rem] = __bfloat16_as_ushort(h); g_wblo_in [rem] = __bfloat16_as_ushort(l); }
}

__global__ void k_nop1() {}
__global__ void k_nop2() {}

// =====================================================================
// core mma loop: warp tile 32(M) x 64(N), K=128, 3-term hi/lo bf16
// B fragment comes from NON-trans ldmatrix of the [n][k] row-major image:
// lanes 0-7 -> n0-7/k0 (b0, n-half0), 8-15 -> n0-7/k8 (b1, half0),
// 16-23 -> n8-15/k0 (b0, half1), 24-31 -> n8-15/k8 (b1, half1).
// =====================================================================
__device__ __forceinline__ void gemm_mma(uint32_t sAhi, uint32_t sAlo,
                                         uint32_t sBhi, uint32_t sBlo,
                                         int lane, int m0, int n0,
                                         float acc[2][8][4]) {
    const int aRow = lane & 15;
    const int aK   = (lane >> 4) << 3;
    const int bRow = (lane & 7) | (((lane >> 4) & 1) << 3);
    const int bK   = ((lane >> 3) & 1) << 3;
#pragma unroll
    for (int kk = 0; kk < 128; kk += 16) {
        uint32_t ah[2][4], al[2][4], bh[4][4], bl[4][4];
#pragma unroll
        for (int mi = 0; mi < 2; mi++) {
            uint32_t off = sw_off(m0 + mi * 16 + aRow, kk + aK);
            LDSM_X4(ah[mi][0], ah[mi][1], ah[mi][2], ah[mi][3], sAhi + off);
            LDSM_X4(al[mi][0], al[mi][1], al[mi][2], al[mi][3], sAlo + off);
        }
#pragma unroll
        for (int nq = 0; nq < 4; nq++) {
            uint32_t off = sw_off(n0 + nq * 16 + bRow, kk + bK);
            LDSM_X4(bh[nq][0], bh[nq][1], bh[nq][2], bh[nq][3], sBhi + off);
            LDSM_X4(bl[nq][0], bl[nq][1], bl[nq][2], bl[nq][3], sBlo + off);
        }
#pragma unroll
        for (int mi = 0; mi < 2; mi++)
#pragma unroll
            for (int nq = 0; nq < 4; nq++)
#pragma unroll
                for (int hf = 0; hf < 2; hf++) {
                    float* d = acc[mi][nq * 2 + hf];
                    MMA16816(d, ah[mi], bh[nq][hf * 2], bh[nq][hf * 2 + 1]);
                    MMA16816(d, al[mi], bh[nq][hf * 2], bh[nq][hf * 2 + 1]);
                    MMA16816(d, ah[mi], bl[nq][hf * 2], bl[nq][hf * 2 + 1]);
                }
    }
}

__device__ __forceinline__ void copy_weights_sw(char* smem, const unsigned short* ghi,
                                                const unsigned short* glo, int t) {
    const uint4* shi = (const uint4*)ghi;
    const uint4* slo = (const uint4*)glo;
#pragma unroll
    for (int i = t; i < 2048; i += 256) {
        int row = i >> 4, chunk = i & 15;
        uint32_t doff = row * 256 + ((((chunk ^ row) & 7) | (chunk & 8)) << 4);
        *(uint4*)(smem + SM_B_HI + doff) = shi[i];
        *(uint4*)(smem + SM_B_LO + doff) = slo[i];
    }
}

// =====================================================================
// K1: in_proj GEMM.  x (B,C,HW) -> xin channels-last (p,c)
// =====================================================================
__global__ void __launch_bounds__(256) k_in_proj(const float* __restrict__ x) {
    extern __shared__ char smem[];
    uint32_t sb = smem_to_u32(smem);
    const int t = threadIdx.x, lane = t & 31, warp = t >> 5;
    const int p0 = blockIdx.x * 128, b = p0 >> 14, hw0 = p0 & 16383;

    copy_weights_sw(smem, g_wbhi_in, g_wblo_in, t);
    // A fill: A[m][k] = x[c=k][p0+m], split hi/lo
    for (int i = t; i < 16384; i += 256) {
        int c = i >> 7, m = i & 127;
        float v = x[(size_t)(b * 128 + c) * HW + hw0 + m];
        __nv_bfloat16 h = __float2bfloat16(v);
        __nv_bfloat16 l = __float2bfloat16(v - __bfloat162float(h));
        uint32_t off = sw_off(m, c);
        *(unsigned short*)(smem + SM_A_HI + off) = __bfloat16_as_ushort(h);
        *(unsigned short*)(smem + SM_A_LO + off) = __bfloat16_as_ushort(l);
    }
    __syncthreads();

    float acc[2][8][4];
#pragma unroll
    for (int i = 0; i < 2; i++)
#pragma unroll
        for (int j = 0; j < 8; j++)
#pragma unroll
            for (int q = 0; q < 4; q++) acc[i][j][q] = 0.f;

    const int m0 = (warp >> 1) * 32, n0 = (warp & 1) * 64;
    gemm_mma(sb + SM_A_HI, sb + SM_A_LO, sb + SM_B_HI, sb + SM_B_LO, lane, m0, n0, acc);

    // epilogue: direct channels-last stores
#pragma unroll
    for (int mi = 0; mi < 2; mi++)
#pragma unroll
        for (int ni = 0; ni < 8; ni++) {
            int row = m0 + mi * 16 + (lane >> 2);
            int col = n0 + ni * 8 + (lane & 3) * 2;
            *(float2*)&g_xin[(size_t)(p0 + row) * 128 + col] =
                make_float2(acc[mi][ni][0], acc[mi][ni][1]);
            *(float2*)&g_xin[(size_t)(p0 + row + 8) * 128 + col] =
                make_float2(acc[mi][ni][2], acc[mi][ni][3]);
        }
}

// =====================================================================
// K2: depthwise 3x3 conv + bias + SiLU (channels-last)
// =====================================================================
__global__ void k_dwsilu(const float* __restrict__ w, const float* __restrict__ bias) {
    __shared__ float sw[9 * 128];
    __shared__ float sb2[128];
    const int t = threadIdx.x;
    for (int i = t; i < 1152; i += 256) {
        int c = i / 9, k = i - c * 9;
        sw[k * 128 + c] = w[i];
    }
    if (t < 128) sb2[t] = bias[t];
    __syncthreads();

    const int p  = blockIdx.x * 8 + (t >> 5);
    const int cg = t & 31;
    const int b = p >> 14, hw = p & 16383, yy = hw >> 7, xx = hw & 127;
    float4 acc = *(const float4*)&sb2[cg * 4];
#pragma unroll
    for (int ky = 0; ky < 3; ky++) {
        int yv = yy + ky - 1;
        if ((unsigned)yv >= (unsigned)Hh) continue;
#pragma unroll
        for (int kx = 0; kx < 3; kx++) {
            int xv = xx + kx - 1;
            if ((unsigned)xv >= (unsigned)Wd) continue;
            float4 v  = *(const float4*)&g_xin[(size_t)(b * HW + yv * Wd + xv) * Cn + cg * 4];
            float4 wv = *(const float4*)&sw[(ky * 3 + kx) * 128 + cg * 4];
            acc.x += wv.x * v.x; acc.y += wv.y * v.y;
            acc.z += wv.z * v.z; acc.w += wv.w * v.w;
        }
    }
    float4 r;
    r.x = acc.x / (1.f + __expf(-acc.x));
    r.y = acc.y / (1.f + __expf(-acc.y));
    r.z = acc.z / (1.f + __expf(-acc.z));
    r.w = acc.w / (1.f + __expf(-acc.w));
    *(float4*)&g_xc[(size_t)p * Cn + cg * 4] = r;
}

__device__ __forceinline__ float softplusf(float x) {
    return fmaxf(x, 0.f) + log1pf(__expf(-fabsf(x)));
}

// =====================================================================
// K3: dwconv(dw_w) -> LN -> GELU -> offsets. one block per pixel.
// =====================================================================
__global__ void k_dw2_off(const float* __restrict__ w, const float* __restrict__ bias,
                          const float* __restrict__ lng, const float* __restrict__ lnb,
                          const float* __restrict__ offw, const float* __restrict__ offb) {
    __shared__ float s[128];
    __shared__ float red[8];
    __shared__ float smr[2];
    const int c = threadIdx.x;
    const int p = blockIdx.x;
    const int b = p >> 14, hw = p & 16383, yy = hw >> 7, xx = hw & 127;

    float acc = bias[c];
#pragma unroll
    for (int ky = 0; ky < 3; ky++) {
        int yv = yy + ky - 1;
        if ((unsigned)yv >= (unsigned)Hh) continue;
#pragma unroll
        for (int kx = 0; kx < 3; kx++) {
            int xv = xx + kx - 1;
            if ((unsigned)xv >= (unsigned)Wd) continue;
            acc += w[c * 9 + ky * 3 + kx] * g_xc[(size_t)(b * HW + yv * Wd + xv) * Cn + c];
        }
    }
    const float v = acc;
    float s1 = v, s2 = v * v;
#pragma unroll
    for (int o = 16; o; o >>= 1) {
        s1 += __shfl_down_sync(0xffffffffu, s1, o);
        s2 += __shfl_down_sync(0xffffffffu, s2, o);
    }
    const int wid = c >> 5;
    if ((c & 31) == 0) { red[wid] = s1; red[4 + wid] = s2; }
    __syncthreads();
    if (c == 0) {
        float a  = red[0] + red[1] + red[2] + red[3];
        float bq = red[4] + red[5] + red[6] + red[7];
        float m  = a * (1.f / 128.f);
        float var = bq * (1.f / 128.f) - m * m;
        smr[0] = m; smr[1] = rsqrtf(var + 1e-6f);
    }
    __syncthreads();
    float xn = (v - smr[0]) * smr[1] * lng[c] + lnb[c];
    s[c] = 0.5f * xn * (1.f + erff(xn * 0.70710678118654752f));
    __syncthreads();
    const int o = c >> 3, seg = c & 7;
    float a2 = 0.f;
#pragma unroll
    for (int k = 0; k < 16; k++) a2 += s[seg * 16 + k] * offw[o * 128 + seg * 16 + k];
#pragma unroll
    for (int d = 4; d; d >>= 1) a2 += __shfl_down_sync(0xffffffffu, a2, d, 8);
    if (seg == 0) g_off[p * 16 + o] = a2 + offb[o];
}

// =====================================================================
// K4: DCNv3 sample + x_dbl + delta precompute (a, bx, C, xd)
// =====================================================================
__global__ void k_dcn_delta(const float* __restrict__ xpw,
                            const float* __restrict__ dtw, const float* __restrict__ dtb,
                            const float* __restrict__ alog) {
    __shared__ float soff[16];
    __shared__ float sxd[128];
    __shared__ float sxb[10];
    const int c = threadIdx.x;
    const int p = blockIdx.x;
    if (c < 16) soff[c] = g_off[p * 16 + c];
    __syncthreads();
    const int b = p >> 14, hw = p & 16383, yy = hw >> 7, xx = hw & 127;
    {
        const int g = c >> 4;
        const float px = (float)xx + soff[g * 2];
        const float py = (float)yy + soff[g * 2 + 1];
        const float x0 = floorf(px), y0 = floorf(py);
        const float wx = px - x0, wy = py - y0;
        float ad = 0.f;
#pragma unroll
        for (int dy = 0; dy < 2; dy++) {
#pragma unroll
            for (int dx = 0; dx < 2; dx++) {
                float yif = y0 + (float)dy, xif = x0 + (float)dx;
                float wgt = (dy ? wy : 1.f - wy) * (dx ? wx : 1.f - wx);
                bool valid = (yif >= 0.f) && (yif < (float)Hh) && (xif >= 0.f) && (xif < (float)Wd);
                int yi = (int)fminf(fmaxf(yif, 0.f), (float)(Hh - 1));
                int xi = (int)fminf(fmaxf(xif, 0.f), (float)(Wd - 1));
                float vv = g_xc[(size_t)(b * HW + yi * Wd + xi) * Cn + c];
                ad += vv * (valid ? wgt : 0.f);
            }
        }
        sxd[c] = ad;
        g_xd[(size_t)p * Cn + c] = ad;
    }
    __syncthreads();
    {
        const int oo = c >> 3, sg = c & 7;
        float a3 = 0.f;
        if (oo < 10) {
#pragma unroll
            for (int k = 0; k < 16; k++)
                a3 += sxd[sg * 16 + k] * xpw[oo * 128 + sg * 16 + k];
        }
#pragma unroll
        for (int d = 4; d; d >>= 1) a3 += __shfl_down_sync(0xffffffffu, a3, d, 8);
        if (sg == 0 && oo < 10) sxb[oo] = a3;
    }
    __syncthreads();
    {
        float4 w0 = *(const float4*)&dtw[c * 8];
        float4 w1 = *(const float4*)&dtw[c * 8 + 4];
        float dtr = dtb[c]
            + w0.x * sxb[0] + w0.y * sxb[1] + w0.z * sxb[2] + w0.w * sxb[3]
            + w1.x * sxb[4] + w1.y * sxb[5] + w1.z * sxb[6] + w1.w * sxb[7];
        float delta = softplusf(dtr);
        float a = __expf(-__expf(alog[c]) * delta);
        g_a [(size_t)p * Cn + c] = a;
        g_bx[(size_t)p * Cn + c] = delta * sxb[8] * sxd[c];
        if (c == 0) g_C[p] = sxb[9];
    }
}

// =====================================================================
// K5/K6/K7: chunked streaming scan
// =====================================================================
__global__ void k_scan1() {
    const int d = threadIdx.x;
    const int chunk = blockIdx.x, b = blockIdx.y;
    float Ar = 1.f, h = 0.f;
    size_t base = ((size_t)(b * HW + chunk * CL)) * Cn + d;
#pragma unroll 4
    for (int i = 0; i < CL; i++) {
        float a  = g_a [base + (size_t)i * Cn];
        float bx = g_bx[base + (size_t)i * Cn];
        Ar *= a;
        h = a * h + bx;
    }
    const int idx = (b * NCH + chunk) * Cn + d;
    g_As[idx] = Ar;
    g_Bs[idx] = h;
}

__global__ void k_scan2() {
    const int b = blockIdx.x, d = threadIdx.x;
    float h = 0.f;
#pragma unroll 4
    for (int ch = 0; ch < NCH; ch++) {
        const int idx = (b * NCH + ch) * Cn + d;
        g_hin[idx] = h;
        h = g_As[idx] * h + g_Bs[idx];
    }
}

__global__ void k_scan3(const float* __restrict__ Ds) {
    const int d = threadIdx.x;
    const int chunk = blockIdx.x, b = blockIdx.y;
    const float Dd = Ds[d];
    float h = g_hin[(b * NCH + chunk) * Cn + d];
    const int pbase = b * HW + chunk * CL;
    size_t base = (size_t)pbase * Cn + d;
#pragma unroll 4
    for (int i = 0; i < CL; i++) {
        float a  = g_a [base + (size_t)i * Cn];
        float bx = g_bx[base + (size_t)i * Cn];
        float xv = g_xd[base + (size_t)i * Cn];
        h = a * h + bx;
        g_y[base + (size_t)i * Cn] = h * g_C[pbase + i] + Dd * xv;
    }
}

// =====================================================================
// K8: out LN (per-lane registers) + out_proj GEMM -> channel-major out
// =====================================================================
__global__ void __launch_bounds__(256) k_out_proj(const float* __restrict__ lng,
                                                  const float* __restrict__ lnb,
                                                  float* __restrict__ out) {
    extern __shared__ char smem[];
    uint32_t sb = smem_to_u32(smem);
    const int t = threadIdx.x, lane = t & 31, warp = t >> 5;
    const int p0 = blockIdx.x * 128, b = p0 >> 14, hw0 = p0 & 16383;

    copy_weights_sw(smem, g_wbhi_out, g_wblo_out, t);

    if (t < 128) {
        // per-lane LN over this pixel's 128 channels
        float v[128];
        const float* src = g_y + (size_t)(p0 + t) * Cn;
        float s1 = 0.f, s2 = 0.f;
#pragma unroll
        for (int q = 0; q < 32; q++) {
            float4 x4 = *(const float4*)&src[q * 4];
            v[q * 4] = x4.x; v[q * 4 + 1] = x4.y; v[q * 4 + 2] = x4.z; v[q * 4 + 3] = x4.w;
            s1 += x4.x + x4.y + x4.z + x4.w;
            s2 += x4.x * x4.x + x4.y * x4.y + x4.z * x4.z + x4.w * x4.w;
        }
        float m = s1 * (1.f / 128.f);
        float var = s2 * (1.f / 128.f) - m * m;
        float rs = rsqrtf(var + 1e-6f);
#pragma unroll
        for (int c = 0; c < 128; c += 2) {
            float a0 = (v[c]     - m) * rs * __ldg(&lng[c])     + __ldg(&lnb[c]);
            float a1 = (v[c + 1] - m) * rs * __ldg(&lng[c + 1]) + __ldg(&lnb[c + 1]);
            __nv_bfloat16 h0 = __float2bfloat16(a0), h1 = __float2bfloat16(a1);
            __nv_bfloat16 l0 = __float2bfloat16(a0 - __bfloat162float(h0));
            __nv_bfloat16 l1 = __float2bfloat16(a1 - __bfloat162float(h1));
            uint32_t off = sw_off(t, c);
            *(uint32_t*)(smem + SM_A_HI + off) =
                (uint32_t)__bfloat16_as_ushort(h0) | ((uint32_t)__bfloat16_as_ushort(h1) << 16);
            *(uint32_t*)(smem + SM_A_LO + off) =
                (uint32_t)__bfloat16_as_ushort(l0) | ((uint32_t)__bfloat16_as_ushort(l1) << 16);
        }
    }
    __syncthreads();

    float acc[2][8][4];
#pragma unroll
    for (int i = 0; i < 2; i++)
#pragma unroll
        for (int j = 0; j < 8; j++)
#pragma unroll
            for (int q = 0; q < 4; q++) acc[i][j][q] = 0.f;

    const int m0 = (warp >> 1) * 32, n0 = (warp & 1) * 64;
    gemm_mma(sb + SM_A_HI, sb + SM_A_LO, sb + SM_B_HI, sb + SM_B_LO, lane, m0, n0, acc);

    __syncthreads();   // done with operand smem; reuse as staging
    float* stg = (float*)smem;   // [128 outputs][132] pixels
#pragma unroll
    for (int mi = 0; mi < 2; mi++)
#pragma unroll
        for (int ni = 0; ni < 8; ni++) {
            int row = m0 + mi * 16 + (lane >> 2);
            int col = n0 + ni * 8 + (lane & 3) * 2;
            stg[(col)     * 132 + row]     = acc[mi][ni][0];
            stg[(col + 1) * 132 + row]     = acc[mi][ni][1];
            stg[(col)     * 132 + row + 8] = acc[mi][ni][2];
            stg[(col + 1) * 132 + row + 8] = acc[mi][ni][3];
        }
    __syncthreads();
    for (int i = t; i < 4096; i += 256) {
        int o = i >> 5, m4 = i & 31;
        float4 v4 = *(const float4*)&stg[o * 132 + m4 * 4];
        *(float4*)&out[(size_t)(b * 128 + o) * HW + hw0 + m4 * 4] = v4;
    }
}

// =====================================================================
extern "C" void kernel_launch(void* const* d_in, const int* in_sizes, int n_in,
                              void* d_out, int out_size) {
    const float* x      = (const float*)d_in[0];
    const float* inw    = (const float*)d_in[1];
    const float* c2w    = (const float*)d_in[2];
    const float* c2b    = (const float*)d_in[3];
    const float* dww    = (const float*)d_in[4];
    const float* dwb    = (const float*)d_in[5];
    const float* dlng   = (const float*)d_in[6];
    const float* dlnb   = (const float*)d_in[7];
    const float* offw   = (const float*)d_in[8];
    const float* offb   = (const float*)d_in[9];
    const float* xpw    = (const float*)d_in[10];
    const float* dtw    = (const float*)d_in[11];
    const float* dtb    = (const float*)d_in[12];
    const float* alog   = (const float*)d_in[13];
    const float* Ds     = (const float*)d_in[14];
    const float* olng   = (const float*)d_in[15];
    const float* olnb   = (const float*)d_in[16];
    const float* outw   = (const float*)d_in[17];
    float* out = (float*)d_out;

    cudaFuncSetAttribute(k_in_proj,  cudaFuncAttributeMaxDynamicSharedMemorySize, SM_GEMM);
    cudaFuncSetAttribute(k_out_proj, cudaFuncAttributeMaxDynamicSharedMemorySize, SM_GEMM);

    k_prep_w<<<128, 256>>>(inw, outw);              // 1
    k_nop1<<<1, 32>>>();                            // 2
    k_nop2<<<1, 32>>>();                            // 3
    k_in_proj<<<P / 128, 256, SM_GEMM>>>(x);        // 4  <- ncu capture slot
    k_dwsilu<<<P / 8, 256>>>(c2w, c2b);             // 5
    k_dw2_off<<<P, 128>>>(dww, dwb, dlng, dlnb, offw, offb);   // 6
    k_dcn_delta<<<P, 128>>>(xpw, dtw, dtb, alog);   // 7
    k_scan1<<<dim3(NCH, Bz), 128>>>();              // 8
    k_scan2<<<Bz, 128>>>();                         // 9
    k_scan3<<<dim3(NCH, Bz), 128>>>(Ds);            // 10
    k_out_proj<<<P / 128, 256, SM_GEMM>>>(olng, olnb, out);    // 11
}

// round 7
// speedup vs baseline: 2.1065x; 1.8183x over previous
#include <cuda_runtime.h>
#include <cuda_bf16.h>
#include <cstdint>

// ---------------- problem constants ----------------
constexpr int Bz = 4, Cn = 128, Hh = 128, Wd = 128;
constexpr int HW = Hh * Wd;       // 16384
constexpr int P  = Bz * HW;       // 65536 pixels
constexpr int NCH = 256, CL = 64; // scan: 256 chunks of 64 steps

// ---------------- scratch ----------------
__device__ float g_xin [P * Cn];
__device__ float g_xc  [P * Cn];
__device__ float g_off [P * 16];
__device__ float g_xd  [P * Cn];
__device__ float g_a   [P * Cn];
__device__ float g_bx  [P * Cn];
__device__ float g_C   [P];
__device__ float g_y   [P * Cn];
__device__ float g_As  [Bz * NCH * Cn];
__device__ float g_Bs  [Bz * NCH * Cn];
__device__ float g_hin [Bz * NCH * Cn];
// bf16 hi/lo weight images, row-major [o][c]
__device__ __align__(16) unsigned short g_wbhi_in [16384];
__device__ __align__(16) unsigned short g_wblo_in [16384];
__device__ __align__(16) unsigned short g_wbhi_out[16384];
__device__ __align__(16) unsigned short g_wblo_out[16384];

__device__ __forceinline__ uint32_t smem_to_u32(const void* p) {
    uint32_t a;
    asm("{ .reg .u64 t; cvta.to.shared.u64 t, %1; cvt.u32.u64 %0, t; }" : "=r"(a) : "l"(p));
    return a;
}

// smem tile layout: row stride 256B (128 bf16), 16B chunks XOR-swizzled by row
__device__ __forceinline__ uint32_t sw_off(int row, int k) {
    int chunk = k >> 3;
    int swch = (chunk & 8) | ((chunk ^ row) & 7);
    return (uint32_t)(row * 256 + swch * 16 + (k & 7) * 2);
}

#define LDSM_X4(r0, r1, r2, r3, addr) \
    asm volatile("ldmatrix.sync.aligned.m8n8.x4.shared.b16 {%0,%1,%2,%3}, [%4];" \
                 : "=r"(r0), "=r"(r1), "=r"(r2), "=r"(r3) : "r"(addr))
#define MMA16816(d, a, b0v, b1v) \
    asm volatile("mma.sync.aligned.m16n8k16.row.col.f32.bf16.bf16.f32 " \
                 "{%0,%1,%2,%3}, {%4,%5,%6,%7}, {%8,%9}, {%0,%1,%2,%3};" \
                 : "+f"((d)[0]), "+f"((d)[1]), "+f"((d)[2]), "+f"((d)[3]) \
                 : "r"((a)[0]), "r"((a)[1]), "r"((a)[2]), "r"((a)[3]), "r"(b0v), "r"(b1v))

// dyn smem layout for GEMM kernels (128KB)
constexpr int SM_A_HI = 0, SM_A_LO = 32768, SM_B_HI = 65536, SM_B_LO = 98304;
constexpr int SM_GEMM = 131072;

// =====================================================================
// K0: split weights into bf16 hi/lo (row-major [o][c])
// =====================================================================
__global__ void k_prep_w(const float* __restrict__ inw, const float* __restrict__ outw) {
    int idx = blockIdx.x * 256 + threadIdx.x;   // 32768 total
    int which = idx >> 14, rem = idx & 16383;
    float v = (which ? outw : inw)[rem];
    __nv_bfloat16 h = __float2bfloat16(v);
    __nv_bfloat16 l = __float2bfloat16(v - __bfloat162float(h));
    if (which) { g_wbhi_out[rem] = __bfloat16_as_ushort(h); g_wblo_out[rem] = __bfloat16_as_ushort(l); }
    else       { g_wbhi_in [rem] = __bfloat16_as_ushort(h); g_wblo_in [rem] = __bfloat16_as_ushort(l); }
}

// =====================================================================
// core mma loop: warp tile 32(M) x 64(N), K=128, 3-term hi/lo bf16
// =====================================================================
__device__ __forceinline__ void gemm_mma(uint32_t sAhi, uint32_t sAlo,
                                         uint32_t sBhi, uint32_t sBlo,
                                         int lane, int m0, int n0,
                                         float acc[2][8][4]) {
    const int aRow = lane & 15;
    const int aK   = (lane >> 4) << 3;
    const int bRow = (lane & 7) | (((lane >> 4) & 1) << 3);
    const int bK   = ((lane >> 3) & 1) << 3;
#pragma unroll
    for (int kk = 0; kk < 128; kk += 16) {
        uint32_t ah[2][4], al[2][4], bh[4][4], bl[4][4];
#pragma unroll
        for (int mi = 0; mi < 2; mi++) {
            uint32_t off = sw_off(m0 + mi * 16 + aRow, kk + aK);
            LDSM_X4(ah[mi][0], ah[mi][1], ah[mi][2], ah[mi][3], sAhi + off);
            LDSM_X4(al[mi][0], al[mi][1], al[mi][2], al[mi][3], sAlo + off);
        }
#pragma unroll
        for (int nq = 0; nq < 4; nq++) {
            uint32_t off = sw_off(n0 + nq * 16 + bRow, kk + bK);
            LDSM_X4(bh[nq][0], bh[nq][1], bh[nq][2], bh[nq][3], sBhi + off);
            LDSM_X4(bl[nq][0], bl[nq][1], bl[nq][2], bl[nq][3], sBlo + off);
        }
#pragma unroll
        for (int mi = 0; mi < 2; mi++)
#pragma unroll
            for (int nq = 0; nq < 4; nq++)
#pragma unroll
                for (int hf = 0; hf < 2; hf++) {
                    float* d = acc[mi][nq * 2 + hf];
                    MMA16816(d, ah[mi], bh[nq][hf * 2], bh[nq][hf * 2 + 1]);
                    MMA16816(d, al[mi], bh[nq][hf * 2], bh[nq][hf * 2 + 1]);
                    MMA16816(d, ah[mi], bl[nq][hf * 2], bl[nq][hf * 2 + 1]);
                }
    }
}

__device__ __forceinline__ void copy_weights_sw(char* smem, const unsigned short* ghi,
                                                const unsigned short* glo, int t) {
    const uint4* shi = (const uint4*)ghi;
    const uint4* slo = (const uint4*)glo;
#pragma unroll
    for (int i = t; i < 2048; i += 256) {
        int row = i >> 4, chunk = i & 15;
        uint32_t doff = row * 256 + ((((chunk ^ row) & 7) | (chunk & 8)) << 4);
        *(uint4*)(smem + SM_B_HI + doff) = shi[i];
        *(uint4*)(smem + SM_B_LO + doff) = slo[i];
    }
}

// =====================================================================
// K1: in_proj GEMM.  x (B,C,HW) -> xin channels-last (p,c)
// =====================================================================
__global__ void __launch_bounds__(256) k_in_proj(const float* __restrict__ x) {
    extern __shared__ char smem[];
    uint32_t sb = smem_to_u32(smem);
    const int t = threadIdx.x, lane = t & 31, warp = t >> 5;
    const int p0 = blockIdx.x * 128, b = p0 >> 14, hw0 = p0 & 16383;

    copy_weights_sw(smem, g_wbhi_in, g_wblo_in, t);
    for (int i = t; i < 16384; i += 256) {
        int c = i >> 7, m = i & 127;
        float v = x[(size_t)(b * 128 + c) * HW + hw0 + m];
        __nv_bfloat16 h = __float2bfloat16(v);
        __nv_bfloat16 l = __float2bfloat16(v - __bfloat162float(h));
        uint32_t off = sw_off(m, c);
        *(unsigned short*)(smem + SM_A_HI + off) = __bfloat16_as_ushort(h);
        *(unsigned short*)(smem + SM_A_LO + off) = __bfloat16_as_ushort(l);
    }
    __syncthreads();

    float acc[2][8][4];
#pragma unroll
    for (int i = 0; i < 2; i++)
#pragma unroll
        for (int j = 0; j < 8; j++)
#pragma unroll
            for (int q = 0; q < 4; q++) acc[i][j][q] = 0.f;

    const int m0 = (warp >> 1) * 32, n0 = (warp & 1) * 64;
    gemm_mma(sb + SM_A_HI, sb + SM_A_LO, sb + SM_B_HI, sb + SM_B_LO, lane, m0, n0, acc);

#pragma unroll
    for (int mi = 0; mi < 2; mi++)
#pragma unroll
        for (int ni = 0; ni < 8; ni++) {
            int row = m0 + mi * 16 + (lane >> 2);
            int col = n0 + ni * 8 + (lane & 3) * 2;
            *(float2*)&g_xin[(size_t)(p0 + row) * 128 + col] =
                make_float2(acc[mi][ni][0], acc[mi][ni][1]);
            *(float2*)&g_xin[(size_t)(p0 + row + 8) * 128 + col] =
                make_float2(acc[mi][ni][2], acc[mi][ni][3]);
        }
}

// =====================================================================
// K2: depthwise 3x3 conv + bias + SiLU (channels-last, warp per pixel)
// =====================================================================
__global__ void k_dwsilu(const float* __restrict__ w, const float* __restrict__ bias) {
    __shared__ float sw[9 * 128];
    __shared__ float sb2[128];
    const int t = threadIdx.x;
    for (int i = t; i < 1152; i += 256) {
        int c = i / 9, k = i - c * 9;
        sw[k * 128 + c] = w[i];
    }
    if (t < 128) sb2[t] = bias[t];
    __syncthreads();

    const int p  = blockIdx.x * 8 + (t >> 5);
    const int cg = t & 31;
    const int b = p >> 14, hw = p & 16383, yy = hw >> 7, xx = hw & 127;
    float4 acc = *(const float4*)&sb2[cg * 4];
#pragma unroll
    for (int ky = 0; ky < 3; ky++) {
        int yv = yy + ky - 1;
        if ((unsigned)yv >= (unsigned)Hh) continue;
#pragma unroll
        for (int kx = 0; kx < 3; kx++) {
            int xv = xx + kx - 1;
            if ((unsigned)xv >= (unsigned)Wd) continue;
            float4 v  = *(const float4*)&g_xc[0];  // placeholder avoided below
            (void)v;
            float4 vv = *(const float4*)&g_xin[(size_t)(b * HW + yv * Wd + xv) * Cn + cg * 4];
            float4 wv = *(const float4*)&sw[(ky * 3 + kx) * 128 + cg * 4];
            acc.x += wv.x * vv.x; acc.y += wv.y * vv.y;
            acc.z += wv.z * vv.z; acc.w += wv.w * vv.w;
        }
    }
    float4 r;
    r.x = acc.x / (1.f + __expf(-acc.x));
    r.y = acc.y / (1.f + __expf(-acc.y));
    r.z = acc.z / (1.f + __expf(-acc.z));
    r.w = acc.w / (1.f + __expf(-acc.w));
    *(float4*)&g_xc[(size_t)p * Cn + cg * 4] = r;
}

__device__ __forceinline__ float softplusf(float x) {
    return fmaxf(x, 0.f) + log1pf(__expf(-fabsf(x)));
}

// =====================================================================
// K3: dwconv(dw_w) -> LN -> GELU -> offsets.  WARP PER PIXEL, no barriers.
// 256 threads = 8 warps = 8 pixels; lane owns 4 channels.
// =====================================================================
__global__ void __launch_bounds__(256) k_dw2_off(const float* __restrict__ w,
                          const float* __restrict__ bias,
                          const float* __restrict__ lng, const float* __restrict__ lnb,
                          const float* __restrict__ offw, const float* __restrict__ offb) {
    __shared__ float sw[9 * 128];
    __shared__ float sb[128], sg[128], sbt[128];
    __shared__ float sofw[16 * 128];
    __shared__ float sofb[16];
    const int t = threadIdx.x;
    for (int i = t; i < 1152; i += 256) {
        int c = i / 9, k = i - c * 9;
        sw[k * 128 + c] = w[i];
    }
    for (int i = t; i < 2048; i += 256) sofw[i] = offw[i];
    if (t < 128) { sb[t] = bias[t]; sg[t] = lng[t]; sbt[t] = lnb[t]; }
    if (t < 16) sofb[t] = offb[t];
    __syncthreads();

    const int p = blockIdx.x * 8 + (t >> 5);
    const int lane = t & 31, c0 = lane * 4;
    const int b = p >> 14, hw = p & 16383, yy = hw >> 7, xx = hw & 127;

    // dwconv + bias
    float4 acc = *(const float4*)&sb[c0];
#pragma unroll
    for (int ky = 0; ky < 3; ky++) {
        int yv = yy + ky - 1;
        if ((unsigned)yv >= (unsigned)Hh) continue;
#pragma unroll
        for (int kx = 0; kx < 3; kx++) {
            int xv = xx + kx - 1;
            if ((unsigned)xv >= (unsigned)Wd) continue;
            float4 v  = *(const float4*)&g_xc[(size_t)(b * HW + yv * Wd + xv) * Cn + c0];
            float4 wv = *(const float4*)&sw[(ky * 3 + kx) * 128 + c0];
            acc.x += wv.x * v.x; acc.y += wv.y * v.y;
            acc.z += wv.z * v.z; acc.w += wv.w * v.w;
        }
    }
    // LN via warp butterfly
    float s1 = acc.x + acc.y + acc.z + acc.w;
    float s2 = acc.x * acc.x + acc.y * acc.y + acc.z * acc.z + acc.w * acc.w;
#pragma unroll
    for (int o = 16; o; o >>= 1) {
        s1 += __shfl_xor_sync(0xffffffffu, s1, o);
        s2 += __shfl_xor_sync(0xffffffffu, s2, o);
    }
    const float m = s1 * (1.f / 128.f);
    const float rs = rsqrtf(s2 * (1.f / 128.f) - m * m + 1e-6f);
    float4 gl = *(const float4*)&sg[c0];
    float4 bl = *(const float4*)&sbt[c0];
    float u[4];
    {
        float xn0 = (acc.x - m) * rs * gl.x + bl.x;
        float xn1 = (acc.y - m) * rs * gl.y + bl.y;
        float xn2 = (acc.z - m) * rs * gl.z + bl.z;
        float xn3 = (acc.w - m) * rs * gl.w + bl.w;
        u[0] = 0.5f * xn0 * (1.f + erff(xn0 * 0.70710678118654752f));
        u[1] = 0.5f * xn1 * (1.f + erff(xn1 * 0.70710678118654752f));
        u[2] = 0.5f * xn2 * (1.f + erff(xn2 * 0.70710678118654752f));
        u[3] = 0.5f * xn3 * (1.f + erff(xn3 * 0.70710678118654752f));
    }
    // offsets: 16 outputs, butterfly-reduced
    float oacc[16];
#pragma unroll
    for (int o = 0; o < 16; o++) {
        float4 wv = *(const float4*)&sofw[o * 128 + c0];
        oacc[o] = u[0] * wv.x + u[1] * wv.y + u[2] * wv.z + u[3] * wv.w;
    }
#pragma unroll
    for (int o = 16; o; o >>= 1)
#pragma unroll
        for (int j = 0; j < 16; j++)
            oacc[j] += __shfl_xor_sync(0xffffffffu, oacc[j], o);
    if (lane < 16) g_off[p * 16 + lane] = oacc[lane] + sofb[lane];
}

// =====================================================================
// K4: DCNv3 sample + x_dbl + delta precompute.  WARP PER PIXEL.
// =====================================================================
__global__ void __launch_bounds__(256) k_dcn_delta(const float* __restrict__ xpw,
                            const float* __restrict__ dtw, const float* __restrict__ dtb,
                            const float* __restrict__ alog) {
    __shared__ float sxp[10 * 128];
    const int t = threadIdx.x;
    for (int i = t; i < 1280; i += 256) sxp[i] = xpw[i];
    __syncthreads();

    const int p = blockIdx.x * 8 + (t >> 5);
    const int lane = t & 31, c0 = lane * 4;
    const int b = p >> 14, hw = p & 16383, yy = hw >> 7, xx = hw & 127;
    const int g = lane >> 2;   // group of channels c0..c0+3

    const float ox = g_off[p * 16 + 2 * g];
    const float oy = g_off[p * 16 + 2 * g + 1];
    const float px = (float)xx + ox, py = (float)yy + oy;
    const float x0 = floorf(px), y0 = floorf(py);
    const float wx = px - x0, wy = py - y0;
    float4 xd = make_float4(0.f, 0.f, 0.f, 0.f);
#pragma unroll
    for (int dy = 0; dy < 2; dy++) {
#pragma unroll
        for (int dx = 0; dx < 2; dx++) {
            float yif = y0 + (float)dy, xif = x0 + (float)dx;
            float wgt = (dy ? wy : 1.f - wy) * (dx ? wx : 1.f - wx);
            bool valid = (yif >= 0.f) && (yif < (float)Hh) && (xif >= 0.f) && (xif < (float)Wd);
            wgt = valid ? wgt : 0.f;
            int yi = (int)fminf(fmaxf(yif, 0.f), (float)(Hh - 1));
            int xi = (int)fminf(fmaxf(xif, 0.f), (float)(Wd - 1));
            float4 v = *(const float4*)&g_xc[(size_t)(b * HW + yi * Wd + xi) * Cn + c0];
            xd.x += v.x * wgt; xd.y += v.y * wgt; xd.z += v.z * wgt; xd.w += v.w * wgt;
        }
    }
    *(float4*)&g_xd[(size_t)p * Cn + c0] = xd;

    // x_dbl = xpw (10x128) @ xd, butterfly
    float xb[10];
#pragma unroll
    for (int r = 0; r < 10; r++) {
        float4 wv = *(const float4*)&sxp[r * 128 + c0];
        xb[r] = xd.x * wv.x + xd.y * wv.y + xd.z * wv.z + xd.w * wv.w;
    }
#pragma unroll
    for (int o = 16; o; o >>= 1)
#pragma unroll
        for (int j = 0; j < 10; j++)
            xb[j] += __shfl_xor_sync(0xffffffffu, xb[j], o);

    // delta -> a, bx per channel
    float4 av, bxv;
    float xdv[4] = {xd.x, xd.y, xd.z, xd.w};
    float* avp = &av.x;
    float* bxp = &bxv.x;
#pragma unroll
    for (int j = 0; j < 4; j++) {
        int c = c0 + j;
        float4 w0 = *(const float4*)&dtw[c * 8];
        float4 w1 = *(const float4*)&dtw[c * 8 + 4];
        float dtr = __ldg(&dtb[c])
            + w0.x * xb[0] + w0.y * xb[1] + w0.z * xb[2] + w0.w * xb[3]
            + w1.x * xb[4] + w1.y * xb[5] + w1.z * xb[6] + w1.w * xb[7];
        float delta = softplusf(dtr);
        avp[j] = __expf(-__expf(__ldg(&alog[c])) * delta);
        bxp[j] = delta * xb[8] * xdv[j];
    }
    *(float4*)&g_a [(size_t)p * Cn + c0] = av;
    *(float4*)&g_bx[(size_t)p * Cn + c0] = bxv;
    if (lane == 0) g_C[p] = xb[9];
}

// =====================================================================
// K5/K6/K7: chunked streaming scan
// =====================================================================
__global__ void k_scan1() {
    const int d = threadIdx.x;
    const int chunk = blockIdx.x, b = blockIdx.y;
    float Ar = 1.f, h = 0.f;
    size_t base = ((size_t)(b * HW + chunk * CL)) * Cn + d;
#pragma unroll 4
    for (int i = 0; i < CL; i++) {
        float a  = g_a [base + (size_t)i * Cn];
        float bx = g_bx[base + (size_t)i * Cn];
        Ar *= a;
        h = a * h + bx;
    }
    const int idx = (b * NCH + chunk) * Cn + d;
    g_As[idx] = Ar;
    g_Bs[idx] = h;
}

__global__ void k_scan2() {
    const int b = blockIdx.x, d = threadIdx.x;
    float h = 0.f;
#pragma unroll 4
    for (int ch = 0; ch < NCH; ch++) {
        const int idx = (b * NCH + ch) * Cn + d;
        g_hin[idx] = h;
        h = g_As[idx] * h + g_Bs[idx];
    }
}

__global__ void k_scan3(const float* __restrict__ Ds) {
    const int d = threadIdx.x;
    const int chunk = blockIdx.x, b = blockIdx.y;
    const float Dd = Ds[d];
    float h = g_hin[(b * NCH + chunk) * Cn + d];
    const int pbase = b * HW + chunk * CL;
    size_t base = (size_t)pbase * Cn + d;
#pragma unroll 4
    for (int i = 0; i < CL; i++) {
        float a  = g_a [base + (size_t)i * Cn];
        float bx = g_bx[base + (size_t)i * Cn];
        float xv = g_xd[base + (size_t)i * Cn];
        h = a * h + bx;
        g_y[base + (size_t)i * Cn] = h * g_C[pbase + i] + Dd * xv;
    }
}

// =====================================================================
// K8: out LN (per-lane registers) + out_proj GEMM -> channel-major out
// =====================================================================
__global__ void __launch_bounds__(256) k_out_proj(const float* __restrict__ lng,
                                                  const float* __restrict__ lnb,
                                                  float* __restrict__ out) {
    extern __shared__ char smem[];
    uint32_t sb = smem_to_u32(smem);
    const int t = threadIdx.x, lane = t & 31, warp = t >> 5;
    const int p0 = blockIdx.x * 128, b = p0 >> 14, hw0 = p0 & 16383;

    copy_weights_sw(smem, g_wbhi_out, g_wblo_out, t);

    if (t < 128) {
        float v[128];
        const float* src = g_y + (size_t)(p0 + t) * Cn;
        float s1 = 0.f, s2 = 0.f;
#pragma unroll
        for (int q = 0; q < 32; q++) {
            float4 x4 = *(const float4*)&src[q * 4];
            v[q * 4] = x4.x; v[q * 4 + 1] = x4.y; v[q * 4 + 2] = x4.z; v[q * 4 + 3] = x4.w;
            s1 += x4.x + x4.y + x4.z + x4.w;
            s2 += x4.x * x4.x + x4.y * x4.y + x4.z * x4.z + x4.w * x4.w;
        }
        float m = s1 * (1.f / 128.f);
        float var = s2 * (1.f / 128.f) - m * m;
        float rs = rsqrtf(var + 1e-6f);
#pragma unroll
        for (int c = 0; c < 128; c += 2) {
            float a0 = (v[c]     - m) * rs * __ldg(&lng[c])     + __ldg(&lnb[c]);
            float a1 = (v[c + 1] - m) * rs * __ldg(&lng[c + 1]) + __ldg(&lnb[c + 1]);
            __nv_bfloat16 h0 = __float2bfloat16(a0), h1 = __float2bfloat16(a1);
            __nv_bfloat16 l0 = __float2bfloat16(a0 - __bfloat162float(h0));
            __nv_bfloat16 l1 = __float2bfloat16(a1 - __bfloat162float(h1));
            uint32_t off = sw_off(t, c);
            *(uint32_t*)(smem + SM_A_HI + off) =
                (uint32_t)__bfloat16_as_ushort(h0) | ((uint32_t)__bfloat16_as_ushort(h1) << 16);
            *(uint32_t*)(smem + SM_A_LO + off) =
                (uint32_t)__bfloat16_as_ushort(l0) | ((uint32_t)__bfloat16_as_ushort(l1) << 16);
        }
    }
    __syncthreads();

    float acc[2][8][4];
#pragma unroll
    for (int i = 0; i < 2; i++)
#pragma unroll
        for (int j = 0; j < 8; j++)
#pragma unroll
            for (int q = 0; q < 4; q++) acc[i][j][q] = 0.f;

    const int m0 = (warp >> 1) * 32, n0 = (warp & 1) * 64;
    gemm_mma(sb + SM_A_HI, sb + SM_A_LO, sb + SM_B_HI, sb + SM_B_LO, lane, m0, n0, acc);

    __syncthreads();
    float* stg = (float*)smem;   // [128 outputs][132] pixels
#pragma unroll
    for (int mi = 0; mi < 2; mi++)
#pragma unroll
        for (int ni = 0; ni < 8; ni++) {
            int row = m0 + mi * 16 + (lane >> 2);
            int col = n0 + ni * 8 + (lane & 3) * 2;
            stg[(col)     * 132 + row]     = acc[mi][ni][0];
            stg[(col + 1) * 132 + row]     = acc[mi][ni][1];
            stg[(col)     * 132 + row + 8] = acc[mi][ni][2];
            stg[(col + 1) * 132 + row + 8] = acc[mi][ni][3];
        }
    __syncthreads();
    for (int i = t; i < 4096; i += 256) {
        int o = i >> 5, m4 = i & 31;
        float4 v4 = *(const float4*)&stg[o * 132 + m4 * 4];
        *(float4*)&out[(size_t)(b * 128 + o) * HW + hw0 + m4 * 4] = v4;
    }
}

// =====================================================================
extern "C" void kernel_launch(void* const* d_in, const int* in_sizes, int n_in,
                              void* d_out, int out_size) {
    const float* x      = (const float*)d_in[0];
    const float* inw    = (const float*)d_in[1];
    const float* c2w    = (const float*)d_in[2];
    const float* c2b    = (const float*)d_in[3];
    const float* dww    = (const float*)d_in[4];
    const float* dwb    = (const float*)d_in[5];
    const float* dlng   = (const float*)d_in[6];
    const float* dlnb   = (const float*)d_in[7];
    const float* offw   = (const float*)d_in[8];
    const float* offb   = (const float*)d_in[9];
    const float* xpw    = (const float*)d_in[10];
    const float* dtw    = (const float*)d_in[11];
    const float* dtb    = (const float*)d_in[12];
    const float* alog   = (const float*)d_in[13];
    const float* Ds     = (const float*)d_in[14];
    const float* olng   = (const float*)d_in[15];
    const float* olnb   = (const float*)d_in[16];
    const float* outw   = (const float*)d_in[17];
    float* out = (float*)d_out;

    cudaFuncSetAttribute(k_in_proj,  cudaFuncAttributeMaxDynamicSharedMemorySize, SM_GEMM);
    cudaFuncSetAttribute(k_out_proj, cudaFuncAttributeMaxDynamicSharedMemorySize, SM_GEMM);

    k_prep_w<<<128, 256>>>(inw, outw);              // 1
    k_in_proj<<<P / 128, 256, SM_GEMM>>>(x);        // 2
    k_dwsilu<<<P / 8, 256>>>(c2w, c2b);             // 3
    k_dw2_off<<<P / 8, 256>>>(dww, dwb, dlng, dlnb, offw, offb);   // 4  <- ncu slot
    k_dcn_delta<<<P / 8, 256>>>(xpw, dtw, dtb, alog);              // 5
    k_scan1<<<dim3(NCH, Bz), 128>>>();              // 6
    k_scan2<<<Bz, 128>>>();                         // 7
    k_scan3<<<dim3(NCH, Bz), 128>>>(Ds);            // 8
    k_out_proj<<<P / 128, 256, SM_GEMM>>>(olng, olnb, out);        // 9
}

// round 8
// speedup vs baseline: 2.2997x; 1.0917x over previous
#include <cuda_runtime.h>
#include <cuda_bf16.h>
#include <cstdint>

// ---------------- problem constants ----------------
constexpr int Bz = 4, Cn = 128, Hh = 128, Wd = 128;
constexpr int HW = Hh * Wd;       // 16384
constexpr int P  = Bz * HW;       // 65536 pixels
constexpr int NCH = 256, CL = 64; // scan: 256 chunks of 64 steps

// ---------------- scratch ----------------
__device__ float g_xin [P * Cn];
__device__ float g_xc  [P * Cn];
__device__ float g_off [P * 16];
__device__ float g_xd  [P * Cn];
__device__ float g_a   [P * Cn];
__device__ float g_bx  [P * Cn];
__device__ float g_C   [P];
__device__ float g_y   [P * Cn];
__device__ float g_As  [Bz * NCH * Cn];
__device__ float g_Bs  [Bz * NCH * Cn];
__device__ float g_hin [Bz * NCH * Cn];
// bf16 hi/lo weight images, row-major [o][c]
__device__ __align__(16) unsigned short g_wbhi_in [16384];
__device__ __align__(16) unsigned short g_wblo_in [16384];
__device__ __align__(16) unsigned short g_wbhi_out[16384];
__device__ __align__(16) unsigned short g_wblo_out[16384];

__device__ __forceinline__ uint32_t smem_to_u32(const void* p) {
    uint32_t a;
    asm("{ .reg .u64 t; cvta.to.shared.u64 t, %1; cvt.u32.u64 %0, t; }" : "=r"(a) : "l"(p));
    return a;
}

// smem tile layout: row stride 256B (128 bf16), 16B chunks XOR-swizzled by row
__device__ __forceinline__ uint32_t sw_off(int row, int k) {
    int chunk = k >> 3;
    int swch = (chunk & 8) | ((chunk ^ row) & 7);
    return (uint32_t)(row * 256 + swch * 16 + (k & 7) * 2);
}

#define LDSM_X4(r0, r1, r2, r3, addr) \
    asm volatile("ldmatrix.sync.aligned.m8n8.x4.shared.b16 {%0,%1,%2,%3}, [%4];" \
                 : "=r"(r0), "=r"(r1), "=r"(r2), "=r"(r3) : "r"(addr))
#define MMA16816(d, a, b0v, b1v) \
    asm volatile("mma.sync.aligned.m16n8k16.row.col.f32.bf16.bf16.f32 " \
                 "{%0,%1,%2,%3}, {%4,%5,%6,%7}, {%8,%9}, {%0,%1,%2,%3};" \
                 : "+f"((d)[0]), "+f"((d)[1]), "+f"((d)[2]), "+f"((d)[3]) \
                 : "r"((a)[0]), "r"((a)[1]), "r"((a)[2]), "r"((a)[3]), "r"(b0v), "r"(b1v))

// dyn smem layout for GEMM kernels (128KB)
constexpr int SM_A_HI = 0, SM_A_LO = 32768, SM_B_HI = 65536, SM_B_LO = 98304;
constexpr int SM_GEMM = 131072;

// =====================================================================
// K0: split weights into bf16 hi/lo (row-major [o][c])
// =====================================================================
__global__ void k_prep_w(const float* __restrict__ inw, const float* __restrict__ outw) {
    int idx = blockIdx.x * 256 + threadIdx.x;   // 32768 total
    int which = idx >> 14, rem = idx & 16383;
    float v = (which ? outw : inw)[rem];
    __nv_bfloat16 h = __float2bfloat16(v);
    __nv_bfloat16 l = __float2bfloat16(v - __bfloat162float(h));
    if (which) { g_wbhi_out[rem] = __bfloat16_as_ushort(h); g_wblo_out[rem] = __bfloat16_as_ushort(l); }
    else       { g_wbhi_in [rem] = __bfloat16_as_ushort(h); g_wblo_in [rem] = __bfloat16_as_ushort(l); }
}

// =====================================================================
// core mma loop: warp tile (MI*16)M x 64N, K=128, 3-term hi/lo bf16
// =====================================================================
template<int MI>
__device__ __forceinline__ void gemm_mma(uint32_t sAhi, uint32_t sAlo,
                                         uint32_t sBhi, uint32_t sBlo,
                                         int lane, int m0, int n0,
                                         float acc[MI][8][4]) {
    const int aRow = lane & 15;
    const int aK   = (lane >> 4) << 3;
    const int bRow = (lane & 7) | (((lane >> 4) & 1) << 3);
    const int bK   = ((lane >> 3) & 1) << 3;
#pragma unroll
    for (int kk = 0; kk < 128; kk += 16) {
        uint32_t ah[MI][4], al[MI][4], bh[4][4], bl[4][4];
#pragma unroll
        for (int mi = 0; mi < MI; mi++) {
            uint32_t off = sw_off(m0 + mi * 16 + aRow, kk + aK);
            LDSM_X4(ah[mi][0], ah[mi][1], ah[mi][2], ah[mi][3], sAhi + off);
            LDSM_X4(al[mi][0], al[mi][1], al[mi][2], al[mi][3], sAlo + off);
        }
#pragma unroll
        for (int nq = 0; nq < 4; nq++) {
            uint32_t off = sw_off(n0 + nq * 16 + bRow, kk + bK);
            LDSM_X4(bh[nq][0], bh[nq][1], bh[nq][2], bh[nq][3], sBhi + off);
            LDSM_X4(bl[nq][0], bl[nq][1], bl[nq][2], bl[nq][3], sBlo + off);
        }
#pragma unroll
        for (int mi = 0; mi < MI; mi++)
#pragma unroll
            for (int nq = 0; nq < 4; nq++)
#pragma unroll
                for (int hf = 0; hf < 2; hf++) {
                    float* d = acc[mi][nq * 2 + hf];
                    MMA16816(d, ah[mi], bh[nq][hf * 2], bh[nq][hf * 2 + 1]);
                    MMA16816(d, al[mi], bh[nq][hf * 2], bh[nq][hf * 2 + 1]);
                    MMA16816(d, ah[mi], bl[nq][hf * 2], bl[nq][hf * 2 + 1]);
                }
    }
}

template<int NT>
__device__ __forceinline__ void copy_weights_sw(char* smem, const unsigned short* ghi,
                                                const unsigned short* glo, int t) {
    const uint4* shi = (const uint4*)ghi;
    const uint4* slo = (const uint4*)glo;
#pragma unroll
    for (int i = t; i < 2048; i += NT) {
        int row = i >> 4, chunk = i & 15;
        uint32_t doff = row * 256 + ((((chunk ^ row) & 7) | (chunk & 8)) << 4);
        *(uint4*)(smem + SM_B_HI + doff) = shi[i];
        *(uint4*)(smem + SM_B_LO + doff) = slo[i];
    }
}

// =====================================================================
// K1: in_proj GEMM.  x (B,C,HW) -> xin channels-last (p,c)
// 512 threads, 16 warps: warp tile 16M x 64N
// =====================================================================
__global__ void __launch_bounds__(512) k_in_proj(const float* __restrict__ x) {
    extern __shared__ char smem[];
    uint32_t sb = smem_to_u32(smem);
    const int t = threadIdx.x, lane = t & 31, warp = t >> 5;
    const int p0 = blockIdx.x * 128, b = p0 >> 14, hw0 = p0 & 16383;

    copy_weights_sw<512>(smem, g_wbhi_in, g_wblo_in, t);
    for (int i = t; i < 16384; i += 512) {
        int c = i >> 7, m = i & 127;
        float v = x[(size_t)(b * 128 + c) * HW + hw0 + m];
        __nv_bfloat16 h = __float2bfloat16(v);
        __nv_bfloat16 l = __float2bfloat16(v - __bfloat162float(h));
        uint32_t off = sw_off(m, c);
        *(unsigned short*)(smem + SM_A_HI + off) = __bfloat16_as_ushort(h);
        *(unsigned short*)(smem + SM_A_LO + off) = __bfloat16_as_ushort(l);
    }
    __syncthreads();

    float acc[1][8][4];
#pragma unroll
    for (int j = 0; j < 8; j++)
#pragma unroll
        for (int q = 0; q < 4; q++) acc[0][j][q] = 0.f;

    const int m0 = (warp >> 1) * 16, n0 = (warp & 1) * 64;
    gemm_mma<1>(sb + SM_A_HI, sb + SM_A_LO, sb + SM_B_HI, sb + SM_B_LO, lane, m0, n0, acc);

#pragma unroll
    for (int ni = 0; ni < 8; ni++) {
        int row = m0 + (lane >> 2);
        int col = n0 + ni * 8 + (lane & 3) * 2;
        *(float2*)&g_xin[(size_t)(p0 + row) * 128 + col] =
            make_float2(acc[0][ni][0], acc[0][ni][1]);
        *(float2*)&g_xin[(size_t)(p0 + row + 8) * 128 + col] =
            make_float2(acc[0][ni][2], acc[0][ni][3]);
    }
}

// =====================================================================
// K2: depthwise 3x3 conv + bias + SiLU. WARP = 4 consecutive pixels.
// 256 threads = 8 warps = 32 pixels/block. Horizontal tap reuse: 18 loads vs 36.
// =====================================================================
__global__ void __launch_bounds__(256) k_dwsilu(const float* __restrict__ w,
                                                const float* __restrict__ bias) {
    __shared__ float sw[9 * 128];
    __shared__ float sb2[128];
    const int t = threadIdx.x;
    for (int i = t; i < 1152; i += 256) {
        int c = i / 9, k = i - c * 9;
        sw[k * 128 + c] = w[i];
    }
    if (t < 128) sb2[t] = bias[t];
    __syncthreads();

    const int warp = t >> 5, lane = t & 31, c0 = lane * 4;
    const int p0 = blockIdx.x * 32 + warp * 4;
    const int b = p0 >> 14, hw = p0 & 16383, yy = hw >> 7, xx0 = hw & 127;

    float4 bv = *(const float4*)&sb2[c0];
    float4 acc[4] = {bv, bv, bv, bv};
#pragma unroll
    for (int ky = 0; ky < 3; ky++) {
        int yv = yy + ky - 1;
        if ((unsigned)yv >= (unsigned)Hh) continue;
        const float* rowb = &g_xin[(size_t)(b * HW + yv * Wd) * Cn + c0];
        float4 v[6];
#pragma unroll
        for (int col = 0; col < 6; col++) {
            int xv = xx0 - 1 + col;
            v[col] = ((unsigned)xv < (unsigned)Wd) ? *(const float4*)&rowb[(size_t)xv * Cn]
                                                   : make_float4(0.f, 0.f, 0.f, 0.f);
        }
        float4 wv[3];
#pragma unroll
        for (int kx = 0; kx < 3; kx++) wv[kx] = *(const float4*)&sw[(ky * 3 + kx) * 128 + c0];
#pragma unroll
        for (int j = 0; j < 4; j++)
#pragma unroll
            for (int kx = 0; kx < 3; kx++) {
                float4 vv = v[j + kx];
                acc[j].x += wv[kx].x * vv.x; acc[j].y += wv[kx].y * vv.y;
                acc[j].z += wv[kx].z * vv.z; acc[j].w += wv[kx].w * vv.w;
            }
    }
#pragma unroll
    for (int j = 0; j < 4; j++) {
        float4 r;
        r.x = acc[j].x / (1.f + __expf(-acc[j].x));
        r.y = acc[j].y / (1.f + __expf(-acc[j].y));
        r.z = acc[j].z / (1.f + __expf(-acc[j].z));
        r.w = acc[j].w / (1.f + __expf(-acc[j].w));
        *(float4*)&g_xc[(size_t)(p0 + j) * Cn + c0] = r;
    }
}

__device__ __forceinline__ float softplusf(float x) {
    return fmaxf(x, 0.f) + log1pf(__expf(-fabsf(x)));
}

// =====================================================================
// K3: dwconv(dw_w) -> LN -> GELU -> offsets.  WARP = 4 pixels.
// =====================================================================
__global__ void __launch_bounds__(256) k_dw2_off(const float* __restrict__ w,
                          const float* __restrict__ bias,
                          const float* __restrict__ lng, const float* __restrict__ lnb,
                          const float* __restrict__ offw, const float* __restrict__ offb) {
    __shared__ float sw[9 * 128];
    __shared__ float sb[128], sg[128], sbt[128];
    __shared__ float sofw[16 * 128];
    __shared__ float sofb[16];
    const int t = threadIdx.x;
    for (int i = t; i < 1152; i += 256) {
        int c = i / 9, k = i - c * 9;
        sw[k * 128 + c] = w[i];
    }
    for (int i = t; i < 2048; i += 256) sofw[i] = offw[i];
    if (t < 128) { sb[t] = bias[t]; sg[t] = lng[t]; sbt[t] = lnb[t]; }
    if (t < 16) sofb[t] = offb[t];
    __syncthreads();

    const int warp = t >> 5, lane = t & 31, c0 = lane * 4;
    const int p0 = blockIdx.x * 32 + warp * 4;
    const int b = p0 >> 14, hw = p0 & 16383, yy = hw >> 7, xx0 = hw & 127;

    // dwconv + bias, 4 pixels with tap reuse
    float4 bv = *(const float4*)&sb[c0];
    float4 acc[4] = {bv, bv, bv, bv};
#pragma unroll
    for (int ky = 0; ky < 3; ky++) {
        int yv = yy + ky - 1;
        if ((unsigned)yv >= (unsigned)Hh) continue;
        const float* rowb = &g_xc[(size_t)(b * HW + yv * Wd) * Cn + c0];
        float4 v[6];
#pragma unroll
        for (int col = 0; col < 6; col++) {
            int xv = xx0 - 1 + col;
            v[col] = ((unsigned)xv < (unsigned)Wd) ? *(const float4*)&rowb[(size_t)xv * Cn]
                                                   : make_float4(0.f, 0.f, 0.f, 0.f);
        }
        float4 wv[3];
#pragma unroll
        for (int kx = 0; kx < 3; kx++) wv[kx] = *(const float4*)&sw[(ky * 3 + kx) * 128 + c0];
#pragma unroll
        for (int j = 0; j < 4; j++)
#pragma unroll
            for (int kx = 0; kx < 3; kx++) {
                float4 vv = v[j + kx];
                acc[j].x += wv[kx].x * vv.x; acc[j].y += wv[kx].y * vv.y;
                acc[j].z += wv[kx].z * vv.z; acc[j].w += wv[kx].w * vv.w;
            }
    }

    // LN (per pixel, butterfly over lanes) + GELU
    float4 gl = *(const float4*)&sg[c0];
    float4 bl = *(const float4*)&sbt[c0];
    float u[4][4];
#pragma unroll
    for (int j = 0; j < 4; j++) {
        float s1 = acc[j].x + acc[j].y + acc[j].z + acc[j].w;
        float s2 = acc[j].x * acc[j].x + acc[j].y * acc[j].y
                 + acc[j].z * acc[j].z + acc[j].w * acc[j].w;
#pragma unroll
        for (int o = 16; o; o >>= 1) {
            s1 += __shfl_xor_sync(0xffffffffu, s1, o);
            s2 += __shfl_xor_sync(0xffffffffu, s2, o);
        }
        const float m = s1 * (1.f / 128.f);
        const float rs = rsqrtf(s2 * (1.f / 128.f) - m * m + 1e-6f);
        float xn0 = (acc[j].x - m) * rs * gl.x + bl.x;
        float xn1 = (acc[j].y - m) * rs * gl.y + bl.y;
        float xn2 = (acc[j].z - m) * rs * gl.z + bl.z;
        float xn3 = (acc[j].w - m) * rs * gl.w + bl.w;
        u[j][0] = 0.5f * xn0 * (1.f + erff(xn0 * 0.70710678118654752f));
        u[j][1] = 0.5f * xn1 * (1.f + erff(xn1 * 0.70710678118654752f));
        u[j][2] = 0.5f * xn2 * (1.f + erff(xn2 * 0.70710678118654752f));
        u[j][3] = 0.5f * xn3 * (1.f + erff(xn3 * 0.70710678118654752f));
    }

    // offsets per pixel (sequential to bound registers)
#pragma unroll
    for (int j = 0; j < 4; j++) {
        float oacc[16];
#pragma unroll
        for (int o = 0; o < 16; o++) {
            float4 wv = *(const float4*)&sofw[o * 128 + c0];
            oacc[o] = u[j][0] * wv.x + u[j][1] * wv.y + u[j][2] * wv.z + u[j][3] * wv.w;
        }
#pragma unroll
        for (int o = 16; o; o >>= 1)
#pragma unroll
            for (int q = 0; q < 16; q++)
                oacc[q] += __shfl_xor_sync(0xffffffffu, oacc[q], o);
        if (lane < 16) g_off[(p0 + j) * 16 + lane] = oacc[lane] + sofb[lane];
    }
}

// =====================================================================
// K4: DCNv3 sample + x_dbl + delta precompute.  WARP PER PIXEL.
// =====================================================================
__global__ void __launch_bounds__(256) k_dcn_delta(const float* __restrict__ xpw,
                            const float* __restrict__ dtw, const float* __restrict__ dtb,
                            const float* __restrict__ alog) {
    __shared__ float sxp[10 * 128];
    const int t = threadIdx.x;
    for (int i = t; i < 1280; i += 256) sxp[i] = xpw[i];
    __syncthreads();

    const int p = blockIdx.x * 8 + (t >> 5);
    const int lane = t & 31, c0 = lane * 4;
    const int b = p >> 14, hw = p & 16383, yy = hw >> 7, xx = hw & 127;
    const int g = lane >> 2;

    const float ox = g_off[p * 16 + 2 * g];
    const float oy = g_off[p * 16 + 2 * g + 1];
    const float px = (float)xx + ox, py = (float)yy + oy;
    const float x0 = floorf(px), y0 = floorf(py);
    const float wx = px - x0, wy = py - y0;
    float4 xd = make_float4(0.f, 0.f, 0.f, 0.f);
#pragma unroll
    for (int dy = 0; dy < 2; dy++) {
#pragma unroll
        for (int dx = 0; dx < 2; dx++) {
            float yif = y0 + (float)dy, xif = x0 + (float)dx;
            float wgt = (dy ? wy : 1.f - wy) * (dx ? wx : 1.f - wx);
            bool valid = (yif >= 0.f) && (yif < (float)Hh) && (xif >= 0.f) && (xif < (float)Wd);
            wgt = valid ? wgt : 0.f;
            int yi = (int)fminf(fmaxf(yif, 0.f), (float)(Hh - 1));
            int xi = (int)fminf(fmaxf(xif, 0.f), (float)(Wd - 1));
            float4 v = *(const float4*)&g_xc[(size_t)(b * HW + yi * Wd + xi) * Cn + c0];
            xd.x += v.x * wgt; xd.y += v.y * wgt; xd.z += v.z * wgt; xd.w += v.w * wgt;
        }
    }
    *(float4*)&g_xd[(size_t)p * Cn + c0] = xd;

    float xb[10];
#pragma unroll
    for (int r = 0; r < 10; r++) {
        float4 wv = *(const float4*)&sxp[r * 128 + c0];
        xb[r] = xd.x * wv.x + xd.y * wv.y + xd.z * wv.z + xd.w * wv.w;
    }
#pragma unroll
    for (int o = 16; o; o >>= 1)
#pragma unroll
        for (int j = 0; j < 10; j++)
            xb[j] += __shfl_xor_sync(0xffffffffu, xb[j], o);

    float4 av, bxv;
    float xdv[4] = {xd.x, xd.y, xd.z, xd.w};
    float* avp = &av.x;
    float* bxp = &bxv.x;
#pragma unroll
    for (int j = 0; j < 4; j++) {
        int c = c0 + j;
        float4 w0 = *(const float4*)&dtw[c * 8];
        float4 w1 = *(const float4*)&dtw[c * 8 + 4];
        float dtr = __ldg(&dtb[c])
            + w0.x * xb[0] + w0.y * xb[1] + w0.z * xb[2] + w0.w * xb[3]
            + w1.x * xb[4] + w1.y * xb[5] + w1.z * xb[6] + w1.w * xb[7];
        float delta = softplusf(dtr);
        avp[j] = __expf(-__expf(__ldg(&alog[c])) * delta);
        bxp[j] = delta * xb[8] * xdv[j];
    }
    *(float4*)&g_a [(size_t)p * Cn + c0] = av;
    *(float4*)&g_bx[(size_t)p * Cn + c0] = bxv;
    if (lane == 0) g_C[p] = xb[9];
}

// =====================================================================
// K5/K6/K7: chunked streaming scan
// =====================================================================
__global__ void k_scan1() {
    const int d = threadIdx.x;
    const int chunk = blockIdx.x, b = blockIdx.y;
    float Ar = 1.f, h = 0.f;
    size_t base = ((size_t)(b * HW + chunk * CL)) * Cn + d;
#pragma unroll 4
    for (int i = 0; i < CL; i++) {
        float a  = g_a [base + (size_t)i * Cn];
        float bx = g_bx[base + (size_t)i * Cn];
        Ar *= a;
        h = a * h + bx;
    }
    const int idx = (b * NCH + chunk) * Cn + d;
    g_As[idx] = Ar;
    g_Bs[idx] = h;
}

__global__ void k_scan2() {
    const int b = blockIdx.x, d = threadIdx.x;
    float h = 0.f;
#pragma unroll 4
    for (int ch = 0; ch < NCH; ch++) {
        const int idx = (b * NCH + ch) * Cn + d;
        g_hin[idx] = h;
        h = g_As[idx] * h + g_Bs[idx];
    }
}

__global__ void k_scan3(const float* __restrict__ Ds) {
    const int d = threadIdx.x;
    const int chunk = blockIdx.x, b = blockIdx.y;
    const float Dd = Ds[d];
    float h = g_hin[(b * NCH + chunk) * Cn + d];
    const int pbase = b * HW + chunk * CL;
    size_t base = (size_t)pbase * Cn + d;
#pragma unroll 4
    for (int i = 0; i < CL; i++) {
        float a  = g_a [base + (size_t)i * Cn];
        float bx = g_bx[base + (size_t)i * Cn];
        float xv = g_xd[base + (size_t)i * Cn];
        h = a * h + bx;
        g_y[base + (size_t)i * Cn] = h * g_C[pbase + i] + Dd * xv;
    }
}

// =====================================================================
// K8: out LN (per-lane registers) + out_proj GEMM -> channel-major out
// 512 threads, 16 warps: warp tile 16M x 64N
// =====================================================================
__global__ void __launch_bounds__(512) k_out_proj(const float* __restrict__ lng,
                                                  const float* __restrict__ lnb,
                                                  float* __restrict__ out) {
    extern __shared__ char smem[];
    uint32_t sb = smem_to_u32(smem);
    const int t = threadIdx.x, lane = t & 31, warp = t >> 5;
    const int p0 = blockIdx.x * 128, b = p0 >> 14, hw0 = p0 & 16383;

    copy_weights_sw<512>(smem, g_wbhi_out, g_wblo_out, t);

    if (t < 128) {
        float v[128];
        const float* src = g_y + (size_t)(p0 + t) * Cn;
        float s1 = 0.f, s2 = 0.f;
#pragma unroll
        for (int q = 0; q < 32; q++) {
            float4 x4 = *(const float4*)&src[q * 4];
            v[q * 4] = x4.x; v[q * 4 + 1] = x4.y; v[q * 4 + 2] = x4.z; v[q * 4 + 3] = x4.w;
            s1 += x4.x + x4.y + x4.z + x4.w;
            s2 += x4.x * x4.x + x4.y * x4.y + x4.z * x4.z + x4.w * x4.w;
        }
        float m = s1 * (1.f / 128.f);
        float var = s2 * (1.f / 128.f) - m * m;
        float rs = rsqrtf(var + 1e-6f);
#pragma unroll
        for (int c = 0; c < 128; c += 2) {
            float a0 = (v[c]     - m) * rs * __ldg(&lng[c])     + __ldg(&lnb[c]);
            float a1 = (v[c + 1] - m) * rs * __ldg(&lng[c + 1]) + __ldg(&lnb[c + 1]);
            __nv_bfloat16 h0 = __float2bfloat16(a0), h1 = __float2bfloat16(a1);
            __nv_bfloat16 l0 = __float2bfloat16(a0 - __bfloat162float(h0));
            __nv_bfloat16 l1 = __float2bfloat16(a1 - __bfloat162float(h1));
            uint32_t off = sw_off(t, c);
            *(uint32_t*)(smem + SM_A_HI + off) =
                (uint32_t)__bfloat16_as_ushort(h0) | ((uint32_t)__bfloat16_as_ushort(h1) << 16);
            *(uint32_t*)(smem + SM_A_LO + off) =
                (uint32_t)__bfloat16_as_ushort(l0) | ((uint32_t)__bfloat16_as_ushort(l1) << 16);
        }
    }
    __syncthreads();

    float acc[1][8][4];
#pragma unroll
    for (int j = 0; j < 8; j++)
#pragma unroll
        for (int q = 0; q < 4; q++) acc[0][j][q] = 0.f;

    const int m0 = (warp >> 1) * 16, n0 = (warp & 1) * 64;
    gemm_mma<1>(sb + SM_A_HI, sb + SM_A_LO, sb + SM_B_HI, sb + SM_B_LO, lane, m0, n0, acc);

    __syncthreads();
    float* stg = (float*)smem;   // [128 outputs][132] pixels
#pragma unroll
    for (int ni = 0; ni < 8; ni++) {
        int row = m0 + (lane >> 2);
        int col = n0 + ni * 8 + (lane & 3) * 2;
        stg[(col)     * 132 + row]     = acc[0][ni][0];
        stg[(col + 1) * 132 + row]     = acc[0][ni][1];
        stg[(col)     * 132 + row + 8] = acc[0][ni][2];
        stg[(col + 1) * 132 + row + 8] = acc[0][ni][3];
    }
    __syncthreads();
    for (int i = t; i < 4096; i += 512) {
        int o = i >> 5, m4 = i & 31;
        float4 v4 = *(const float4*)&stg[o * 132 + m4 * 4];
        *(float4*)&out[(size_t)(b * 128 + o) * HW + hw0 + m4 * 4] = v4;
    }
}

// =====================================================================
extern "C" void kernel_launch(void* const* d_in, const int* in_sizes, int n_in,
                              void* d_out, int out_size) {
    const float* x      = (const float*)d_in[0];
    const float* inw    = (const float*)d_in[1];
    const float* c2w    = (const float*)d_in[2];
    const float* c2b    = (const float*)d_in[3];
    const float* dww    = (const float*)d_in[4];
    const float* dwb    = (const float*)d_in[5];
    const float* dlng   = (const float*)d_in[6];
    const float* dlnb   = (const float*)d_in[7];
    const float* offw   = (const float*)d_in[8];
    const float* offb   = (const float*)d_in[9];
    const float* xpw    = (const float*)d_in[10];
    const float* dtw    = (const float*)d_in[11];
    const float* dtb    = (const float*)d_in[12];
    const float* alog   = (const float*)d_in[13];
    const float* Ds     = (const float*)d_in[14];
    const float* olng   = (const float*)d_in[15];
    const float* olnb   = (const float*)d_in[16];
    const float* outw   = (const float*)d_in[17];
    float* out = (float*)d_out;

    cudaFuncSetAttribute(k_in_proj,  cudaFuncAttributeMaxDynamicSharedMemorySize, SM_GEMM);
    cudaFuncSetAttribute(k_out_proj, cudaFuncAttributeMaxDynamicSharedMemorySize, SM_GEMM);

    k_prep_w<<<128, 256>>>(inw, outw);              // 1
    k_in_proj<<<P / 128, 512, SM_GEMM>>>(x);        // 2
    k_dwsilu<<<P / 32, 256>>>(c2w, c2b);            // 3
    k_dw2_off<<<P / 32, 256>>>(dww, dwb, dlng, dlnb, offw, offb);  // 4  <- ncu slot
    k_dcn_delta<<<P / 8, 256>>>(xpw, dtw, dtb, alog);              // 5
    k_scan1<<<dim3(NCH, Bz), 128>>>();              // 6
    k_scan2<<<Bz, 128>>>();                         // 7
    k_scan3<<<dim3(NCH, Bz), 128>>>(Ds);            // 8
    k_out_proj<<<P / 128, 512, SM_GEMM>>>(olng, olnb, out);        // 9
}